// round 2
// baseline (speedup 1.0000x reference)
#include <cuda_runtime.h>
#include <cuda_bf16.h>
#include <cstdint>

// ---------------------------------------------------------------------------
// TernaryConv2d: out = conv2d(x, ternary(w, 0.05*max|w|), VALID) + bias
// x: [32,128,56,56] f32, w: [256,128,3,3] f32, bias: [256] f32
// out: [32,256,54,54] f32
// ---------------------------------------------------------------------------

#define NN   32
#define CC   128
#define HH   56
#define WW   56
#define OCH  256
#define OHH  54
#define OWW  54

#define OCT  32   // oc per block
#define RT   6    // output rows per block
#define NTHR 324  // 54 x 6

// Scratch: quantized weights, padded layout [ic][oc][12] (k=0..8 data, 9..11 zero)
__device__ float    g_qw[CC * OCH * 12];
__device__ unsigned g_wmax_bits;

// ---- kernel 0: reset max ----
__global__ void k_init() { g_wmax_bits = 0u; }

// ---- kernel 1: abs-max reduction over 256*128*9 weights ----
__global__ void k_max(const float* __restrict__ w, int n) {
    float m = 0.f;
    for (int i = blockIdx.x * blockDim.x + threadIdx.x; i < n; i += gridDim.x * blockDim.x)
        m = fmaxf(m, fabsf(w[i]));
#pragma unroll
    for (int o = 16; o > 0; o >>= 1)
        m = fmaxf(m, __shfl_xor_sync(0xffffffffu, m, o));
    __shared__ float sm[32];
    int lane = threadIdx.x & 31, wid = threadIdx.x >> 5;
    if (lane == 0) sm[wid] = m;
    __syncthreads();
    if (threadIdx.x < 32) {
        int nw = (blockDim.x + 31) >> 5;
        m = (threadIdx.x < nw) ? sm[threadIdx.x] : 0.f;
#pragma unroll
        for (int o = 16; o > 0; o >>= 1)
            m = fmaxf(m, __shfl_xor_sync(0xffffffffu, m, o));
        if (threadIdx.x == 0)
            atomicMax(&g_wmax_bits, __float_as_uint(m));  // |w|>=0 -> bit order == float order
    }
}

// ---- kernel 2: quantize into padded transposed layout g_qw[ic][oc][12] ----
__global__ void k_quant(const float* __restrict__ w) {
    int idx = blockIdx.x * blockDim.x + threadIdx.x;            // over CC*OCH*12
    if (idx >= CC * OCH * 12) return;
    int k  = idx % 12;
    int oc = (idx / 12) % OCH;
    int ic = idx / (12 * OCH);
    float q = 0.f;
    if (k < 9) {
        float t  = 0.05f * __uint_as_float(g_wmax_bits);
        float wv = w[(oc * CC + ic) * 9 + k];
        q = (wv > t ? 1.f : 0.f) - (wv < -t ? 1.f : 0.f);
    }
    g_qw[idx] = q;
}

// ---- kernel 3: direct conv ----
// grid: (8 oc-tiles, 9 row-tiles, 32 n); block: (54, 6)
__global__ __launch_bounds__(NTHR) void k_conv(const float* __restrict__ x,
                                               const float* __restrict__ bias,
                                               float* __restrict__ out) {
    __shared__ float s_in[8 * WW];        // 8 input rows x 56
    __shared__ float s_w[OCT * 12];       // 32 oc x 12 (9 used)

    const int tx  = threadIdx.x;          // 0..53 = ow
    const int ty  = threadIdx.y;          // 0..5
    const int tid = ty * 54 + tx;
    const int n   = blockIdx.z;
    const int oh0 = blockIdx.y * RT;
    const int oc0 = blockIdx.x * OCT;

    float acc[OCT];
#pragma unroll
    for (int j = 0; j < OCT; j++) acc[j] = 0.f;

    const float* xin = x + (size_t)n * CC * HH * WW;

    for (int ic = 0; ic < CC; ic++) {
        // stage input patch: rows [oh0, oh0+8) x 56 cols  (448 floats = 112 float4)
        const float4* src = (const float4*)(xin + (size_t)ic * HH * WW + (size_t)oh0 * WW);
        for (int i = tid; i < 112; i += NTHR)
            ((float4*)s_in)[i] = src[i];
        // stage weights for this ic: 32 oc x 12 floats = 96 float4 (contiguous in g_qw)
        const float4* wsrc = (const float4*)(g_qw + ((size_t)ic * OCH + oc0) * 12);
        if (tid < 96)
            ((float4*)s_w)[tid] = wsrc[tid];
        __syncthreads();

        const float i00 = s_in[(ty + 0) * WW + tx + 0];
        const float i01 = s_in[(ty + 0) * WW + tx + 1];
        const float i02 = s_in[(ty + 0) * WW + tx + 2];
        const float i10 = s_in[(ty + 1) * WW + tx + 0];
        const float i11 = s_in[(ty + 1) * WW + tx + 1];
        const float i12 = s_in[(ty + 1) * WW + tx + 2];
        const float i20 = s_in[(ty + 2) * WW + tx + 0];
        const float i21 = s_in[(ty + 2) * WW + tx + 1];
        const float i22 = s_in[(ty + 2) * WW + tx + 2];

#pragma unroll
        for (int j = 0; j < OCT; j++) {
            const float4 a = *(const float4*)(s_w + j * 12 + 0);
            const float4 b = *(const float4*)(s_w + j * 12 + 4);
            const float  w8 = s_w[j * 12 + 8];
            acc[j] += a.x * i00 + a.y * i01 + a.z * i02
                    + a.w * i10 + b.x * i11 + b.y * i12
                    + b.z * i20 + b.w * i21 + w8 * i22;
        }
        __syncthreads();
    }

    const int oh = oh0 + ty;
    const int ow = tx;
#pragma unroll
    for (int j = 0; j < OCT; j++) {
        const int oc = oc0 + j;
        out[(((size_t)n * OCH + oc) * OHH + oh) * OWW + ow] = acc[j] + bias[oc];
    }
}

extern "C" void kernel_launch(void* const* d_in, const int* in_sizes, int n_in,
                              void* d_out, int out_size) {
    const float* x    = (const float*)d_in[0];
    const float* w    = (const float*)d_in[1];
    const float* bias = (const float*)d_in[2];
    float*       out  = (float*)d_out;

    const int wn = OCH * CC * 9;

    k_init<<<1, 1>>>();
    k_max<<<256, 256>>>(w, wn);
    {
        int total = CC * OCH * 12;
        k_quant<<<(total + 255) / 256, 256>>>(w);
    }
    {
        dim3 grid(OCH / OCT, OHH / RT, NN);   // (8, 9, 32)
        dim3 block(54, 6);
        k_conv<<<grid, block>>>(x, bias, out);
    }
    (void)in_sizes; (void)n_in; (void)out_size;
}

// round 6
// speedup vs baseline: 5.7686x; 5.7686x over previous
#include <cuda_runtime.h>
#include <cstdint>

// ---------------------------------------------------------------------------
// TernaryConv2d via mma.sync (HMMA tf32) implicit GEMM, tap-shift indexing.
// x: [32,128,56,56] f32, w: [256,128,3,3] f32, bias:[256] -> out:[32,256,54,54]
// ---------------------------------------------------------------------------

#define CC    128
#define HHH   56
#define WID   56
#define OCH   256
#define OHH   54
#define OWW   54

#define NTHR   512
#define ICK    16          // ic per chunk
#define NCHUNK 8
#define BCOLS  68          // staged input cols (64 + 2 halo, padded)
#define BROWS  6           // 4 out rows + 2 halo
#define BPIX   (BROWS * BCOLS)          // 408 pixels
#define A_FLOATS_CHUNK (9 * 2 * 8 * 32 * 4)   // tap*kstep*mtile*lane*4 = 18432
#define A_BYTES_CHUNK  (A_FLOATS_CHUNK * 4)   // 73728
#define B_BYTES        (ICK * BPIX * 4)       // 26112
#define SMEM_DYN       (A_BYTES_CHUNK + B_BYTES + 256)

__device__ float    g_qw[2 * NCHUNK * A_FLOATS_CHUNK];   // 294912 floats
__device__ unsigned g_wmax_bits;

// ------------------------- preprocessing ----------------------------------
__global__ void k_init() { g_wmax_bits = 0u; }

__global__ void k_max(const float* __restrict__ w, int n) {
    float m = 0.f;
    for (int i = blockIdx.x * blockDim.x + threadIdx.x; i < n; i += gridDim.x * blockDim.x)
        m = fmaxf(m, fabsf(w[i]));
#pragma unroll
    for (int o = 16; o > 0; o >>= 1) m = fmaxf(m, __shfl_xor_sync(~0u, m, o));
    __shared__ float sm[32];
    int lane = threadIdx.x & 31, wd = threadIdx.x >> 5;
    if (lane == 0) sm[wd] = m;
    __syncthreads();
    if (threadIdx.x < 32) {
        int nw = (blockDim.x + 31) >> 5;
        m = (threadIdx.x < nw) ? sm[threadIdx.x] : 0.f;
#pragma unroll
        for (int o = 16; o > 0; o >>= 1) m = fmaxf(m, __shfl_xor_sync(~0u, m, o));
        if (threadIdx.x == 0) atomicMax(&g_wmax_bits, __float_as_uint(m));
    }
}

// quantize weights straight into mma A-fragment order:
// g_qw[(half*8+chunk)*18432 + (((tap*2+kstep)*8+mtile)*32 + lane)*4 + r]
//   r0=(g,k) r1=(g+8,k) r2=(g,k+4) r3=(g+8,k+4); g=lane/4, k=lane%4
__global__ void k_quant(const float* __restrict__ w) {
    int idx = blockIdx.x * blockDim.x + threadIdx.x;
    if (idx >= 2 * NCHUNK * A_FLOATS_CHUNK) return;
    int half  = idx / (NCHUNK * A_FLOATS_CHUNK);
    int r1    = idx % (NCHUNK * A_FLOATS_CHUNK);
    int chunk = r1 / A_FLOATS_CHUNK;
    int r2    = r1 % A_FLOATS_CHUNK;
    int frag  = r2 >> 7;            // tap*16 + kstep*8 + mtile
    int within = r2 & 127;          // lane*4 + r
    int tap   = frag >> 4;
    int kstep = (frag >> 3) & 1;
    int mtile = frag & 7;
    int lane  = within >> 2;
    int r     = within & 3;
    int g  = lane >> 2, t4 = lane & 3;
    int oc = half * 128 + mtile * 16 + g + 8 * (r & 1);
    int ic = chunk * ICK + kstep * 8 + t4 + 4 * (r >> 1);
    float t  = 0.05f * __uint_as_float(g_wmax_bits);
    float wv = w[(oc * CC + ic) * 9 + tap];
    g_qw[idx] = (wv > t ? 1.f : 0.f) - (wv < -t ? 1.f : 0.f);
}

// ------------------------- mma helper --------------------------------------
__device__ __forceinline__ void mma8(float* c, const float4& a, uint32_t b0, uint32_t b1) {
    const uint32_t* ai = (const uint32_t*)&a;
    asm volatile(
        "mma.sync.aligned.m16n8k8.row.col.f32.tf32.tf32.f32 "
        "{%0,%1,%2,%3}, {%4,%5,%6,%7}, {%8,%9}, {%0,%1,%2,%3};"
        : "+f"(c[0]), "+f"(c[1]), "+f"(c[2]), "+f"(c[3])
        : "r"(ai[0]), "r"(ai[1]), "r"(ai[2]), "r"(ai[3]), "r"(b0), "r"(b1));
}

// ------------------------- conv kernel --------------------------------------
// grid (2 oc-halves, 14 row-groups, 32 n), block 512
__global__ __launch_bounds__(NTHR, 1) void k_conv(const float* __restrict__ x,
                                                  const float* __restrict__ bias,
                                                  float* __restrict__ out) {
    extern __shared__ char smem[];
    float*    As = (float*)smem;                         // 18432 floats
    uint32_t* Bs = (uint32_t*)(smem + A_BYTES_CHUNK);    // [ic16][pix 408]

    const int tid    = threadIdx.x;
    const int wid    = tid >> 5;
    const int lane   = tid & 31;
    const int warp_m = wid & 3;       // 32-oc group
    const int warp_n = wid >> 2;      // output row within row-group
    const int g      = lane >> 2;
    const int t4     = lane & 3;
    const int half   = blockIdx.x;
    const int rg     = blockIdx.y;
    const int n      = blockIdx.z;

    float acc[2][8][4];
#pragma unroll
    for (int mi = 0; mi < 2; mi++)
#pragma unroll
        for (int ni = 0; ni < 8; ni++)
#pragma unroll
            for (int r = 0; r < 4; r++) acc[mi][ni][r] = 0.f;

    const float* xin = x + (size_t)n * CC * HHH * WID;

    for (int chunk = 0; chunk < NCHUNK; chunk++) {
        if (chunk) __syncthreads();   // smem reuse barrier

        // ---- stage A: linear cp.async (fragment-ordered weights)
        {
            const float4* src = (const float4*)(g_qw + (size_t)(half * NCHUNK + chunk) * A_FLOATS_CHUNK);
            uint32_t dst;
            asm("{ .reg .u64 t; cvta.to.shared.u64 t, %1; cvt.u32.u64 %0, t; }"
                : "=r"(dst) : "l"((void*)As));
#pragma unroll
            for (int i = 0; i < A_BYTES_CHUNK / 16 / NTHR; i++) {
                int e = i * NTHR + tid;
                asm volatile("cp.async.cg.shared.global [%0], [%1], 16;"
                             :: "r"(dst + e * 16), "l"(src + e) : "memory");
            }
            asm volatile("cp.async.commit_group;" ::: "memory");
        }
        // ---- stage B: [ic][row][col] tf32, linear STS (addr == loop index)
        {
            const int ic0 = chunk * ICK;
            for (int i = tid; i < ICK * BPIX; i += NTHR) {
                int col   = i % BCOLS;
                int rowic = i / BCOLS;
                int row   = rowic % BROWS;
                int ic    = rowic / BROWS;
                int inrow = rg * 4 + row;
                float v = 0.f;
                if (col < WID && inrow < HHH)
                    v = xin[(size_t)(ic0 + ic) * (HHH * WID) + inrow * WID + col];
                uint32_t tv;
                asm("cvt.rna.tf32.f32 %0, %1;" : "=r"(tv) : "f"(v));
                Bs[i] = tv;
            }
        }
        asm volatile("cp.async.wait_group 0;" ::: "memory");
        __syncthreads();

        // ---- compute: 9 taps x 2 ksteps x (2 mtiles x 8 nfrags) mma
        const float4* Af = (const float4*)As;
        for (int tap = 0; tap < 9; tap++) {
            const int kh = tap / 3, kw = tap - 3 * kh;
            const int prow = (warp_n + kh) * BCOLS + g + kw;   // pixel base
#pragma unroll
            for (int kstep = 0; kstep < 2; kstep++) {
                const int fbase = ((tap * 2 + kstep) * 8 + warp_m * 2) * 32 + lane;
                const float4 A0 = Af[fbase];
                const float4 A1 = Af[fbase + 32];
                const int kk = t4 + kstep * 8;
                const uint32_t* B0 = Bs + kk * BPIX + prow;
                const uint32_t* B1 = B0 + 4 * BPIX;
#pragma unroll
                for (int ni = 0; ni < 8; ni++) {
                    uint32_t b0 = B0[ni * 8];
                    uint32_t b1 = B1[ni * 8];
                    mma8(acc[0][ni], A0, b0, b1);
                    mma8(acc[1][ni], A1, b0, b1);
                }
            }
        }
    }

    // ---- epilogue
    const int oh = rg * 4 + warp_n;
    if (oh < OHH) {
#pragma unroll
        for (int mi = 0; mi < 2; mi++) {
            const int oc0 = half * 128 + warp_m * 32 + mi * 16 + g;
            const float bv0 = bias[oc0];
            const float bv1 = bias[oc0 + 8];
            float* o0 = out + ((size_t)n * OCH + oc0) * (OHH * OWW) + oh * OWW;
            float* o1 = o0 + 8 * (OHH * OWW);
#pragma unroll
            for (int ni = 0; ni < 7; ni++) {
                const int ow = ni * 8 + 2 * t4;
                if (ow < OWW) {       // ow even; pair fully valid iff ow<54
                    float2 v0 = make_float2(acc[mi][ni][0] + bv0, acc[mi][ni][1] + bv0);
                    float2 v1 = make_float2(acc[mi][ni][2] + bv1, acc[mi][ni][3] + bv1);
                    *(float2*)(o0 + ow) = v0;
                    *(float2*)(o1 + ow) = v1;
                }
            }
        }
    }
}

// ------------------------- launch -------------------------------------------
extern "C" void kernel_launch(void* const* d_in, const int* in_sizes, int n_in,
                              void* d_out, int out_size) {
    const float* x    = (const float*)d_in[0];
    const float* w    = (const float*)d_in[1];
    const float* bias = (const float*)d_in[2];
    float*       out  = (float*)d_out;

    k_init<<<1, 1>>>();
    k_max<<<256, 256>>>(w, OCH * CC * 9);
    k_quant<<<(2 * NCHUNK * A_FLOATS_CHUNK + 255) / 256, 256>>>(w);

    cudaFuncSetAttribute(k_conv, cudaFuncAttributeMaxDynamicSharedMemorySize, SMEM_DYN);
    dim3 grid(2, 14, 32);
    k_conv<<<grid, NTHR, SMEM_DYN>>>(x, bias, out);

    (void)in_sizes; (void)n_in; (void)out_size;
}

// round 7
// speedup vs baseline: 8.5052x; 1.4744x over previous
#include <cuda_runtime.h>
#include <cstdint>

// ---------------------------------------------------------------------------
// TernaryConv2d via mma.sync (HMMA tf32) implicit GEMM, tap-shift indexing,
// double-buffered cp.async pipeline (raw-f32 B operands, HW tf32 truncation).
// x: [32,128,56,56] f32, w: [256,128,3,3] f32, bias:[256] -> out:[32,256,54,54]
// ---------------------------------------------------------------------------

#define CC    128
#define HHH   56
#define WID   56
#define OCH   256
#define OHH   54
#define OWW   54

#define NTHR   512
#define ICK    16          // ic per chunk
#define NCHUNK 8
#define BCOLS  68          // staged input cols (64 + 2 halo, padded)
#define BROWS  6           // 4 out rows + 2 halo
#define BPIX   (BROWS * BCOLS)                 // 408 pixels
#define A_FLOATS_CHUNK (9 * 2 * 8 * 32 * 4)    // 18432
#define A_BYTES_CHUNK  (A_FLOATS_CHUNK * 4)    // 73728
#define B_BYTES        (ICK * BPIX * 4)        // 26112
#define STAGE_BYTES    (A_BYTES_CHUNK + B_BYTES)   // 99840
#define SMEM_DYN       (2 * STAGE_BYTES)           // 199680

__device__ float    g_qw[2 * NCHUNK * A_FLOATS_CHUNK];
__device__ unsigned g_wmax_bits;

// ------------------------- preprocessing ----------------------------------
__global__ void k_init() { g_wmax_bits = 0u; }

__global__ void k_max(const float* __restrict__ w, int n) {
    float m = 0.f;
    for (int i = blockIdx.x * blockDim.x + threadIdx.x; i < n; i += gridDim.x * blockDim.x)
        m = fmaxf(m, fabsf(w[i]));
#pragma unroll
    for (int o = 16; o > 0; o >>= 1) m = fmaxf(m, __shfl_xor_sync(~0u, m, o));
    __shared__ float sm[32];
    int lane = threadIdx.x & 31, wd = threadIdx.x >> 5;
    if (lane == 0) sm[wd] = m;
    __syncthreads();
    if (threadIdx.x < 32) {
        int nw = (blockDim.x + 31) >> 5;
        m = (threadIdx.x < nw) ? sm[threadIdx.x] : 0.f;
#pragma unroll
        for (int o = 16; o > 0; o >>= 1) m = fmaxf(m, __shfl_xor_sync(~0u, m, o));
        if (threadIdx.x == 0) atomicMax(&g_wmax_bits, __float_as_uint(m));
    }
}

// quantize weights straight into mma A-fragment order:
// g_qw[(half*8+chunk)*18432 + (((tap*2+kstep)*8+mtile)*32 + lane)*4 + r]
__global__ void k_quant(const float* __restrict__ w) {
    int idx = blockIdx.x * blockDim.x + threadIdx.x;
    if (idx >= 2 * NCHUNK * A_FLOATS_CHUNK) return;
    int half  = idx / (NCHUNK * A_FLOATS_CHUNK);
    int r1    = idx % (NCHUNK * A_FLOATS_CHUNK);
    int chunk = r1 / A_FLOATS_CHUNK;
    int r2    = r1 % A_FLOATS_CHUNK;
    int frag  = r2 >> 7;
    int within = r2 & 127;
    int tap   = frag >> 4;
    int kstep = (frag >> 3) & 1;
    int mtile = frag & 7;
    int lane  = within >> 2;
    int r     = within & 3;
    int g  = lane >> 2, t4 = lane & 3;
    int oc = half * 128 + mtile * 16 + g + 8 * (r & 1);
    int ic = chunk * ICK + kstep * 8 + t4 + 4 * (r >> 1);
    float t  = 0.05f * __uint_as_float(g_wmax_bits);
    float wv = w[(oc * CC + ic) * 9 + tap];
    g_qw[idx] = (wv > t ? 1.f : 0.f) - (wv < -t ? 1.f : 0.f);
}

// ------------------------- helpers -----------------------------------------
__device__ __forceinline__ void mma8(float* c, const float4& a, uint32_t b0, uint32_t b1) {
    const uint32_t* ai = (const uint32_t*)&a;
    asm volatile(
        "mma.sync.aligned.m16n8k8.row.col.f32.tf32.tf32.f32 "
        "{%0,%1,%2,%3}, {%4,%5,%6,%7}, {%8,%9}, {%0,%1,%2,%3};"
        : "+f"(c[0]), "+f"(c[1]), "+f"(c[2]), "+f"(c[3])
        : "r"(ai[0]), "r"(ai[1]), "r"(ai[2]), "r"(ai[3]), "r"(b0), "r"(b1));
}

__device__ __forceinline__ uint32_t smem_u32(const void* p) {
    uint32_t a;
    asm("{ .reg .u64 t; cvta.to.shared.u64 t, %1; cvt.u32.u64 %0, t; }" : "=r"(a) : "l"(p));
    return a;
}

__device__ __forceinline__ void cpa16(uint32_t dst, const void* src) {
    asm volatile("cp.async.cg.shared.global [%0], [%1], 16;" :: "r"(dst), "l"(src) : "memory");
}

// issue all cp.async for one chunk into stage buffer at smem addr `sbase`
__device__ __forceinline__ void stage_chunk(uint32_t sbase, int chunk, int half,
                                            int rg, int tid, const float* xin) {
    // A: 4608 float4, linear, 9 per thread
    const float4* asrc = (const float4*)(g_qw + (size_t)(half * NCHUNK + chunk) * A_FLOATS_CHUNK);
#pragma unroll
    for (int i = 0; i < 9; i++) {
        int e = i * NTHR + tid;
        cpa16(sbase + e * 16, asrc + e);
    }
    // B: 16 ic x 6 rows x 14 float4 (cols 0..55); pads stay zero
    const uint32_t bdst = sbase + A_BYTES_CHUNK;
    const int ic0 = chunk * ICK;
#pragma unroll
    for (int it = 0; it < 3; it++) {
        int i = it * NTHR + tid;
        if (i < ICK * BROWS * 14) {
            int c4    = i % 14;
            int rowic = i / 14;
            int row   = rowic % BROWS;
            int ic    = rowic / BROWS;
            int inrow = rg * 4 + row;
            if (inrow < HHH) {
                const float4* s = (const float4*)(xin + (size_t)(ic0 + ic) * (HHH * WID)
                                                  + inrow * WID) + c4;
                cpa16(bdst + ((ic * BROWS + row) * BCOLS + c4 * 4) * 4, s);
            }
        }
    }
    asm volatile("cp.async.commit_group;" ::: "memory");
}

// ------------------------- conv kernel --------------------------------------
// grid (2 oc-halves, 14 row-groups, 32 n), block 512
__global__ __launch_bounds__(NTHR, 1) void k_conv(const float* __restrict__ x,
                                                  const float* __restrict__ bias,
                                                  float* __restrict__ out) {
    extern __shared__ char smem[];
    const uint32_t sb = smem_u32(smem);

    const int tid    = threadIdx.x;
    const int wid    = tid >> 5;
    const int lane   = tid & 31;
    const int warp_m = wid & 3;
    const int warp_n = wid >> 2;
    const int g      = lane >> 2;
    const int t4     = lane & 3;
    const int half   = blockIdx.x;
    const int rg     = blockIdx.y;
    const int n      = blockIdx.z;

    // one-time zero of both B buffers (covers halo cols + oob rows)
    for (int s = 0; s < 2; s++) {
        uint32_t* B = (uint32_t*)(smem + s * STAGE_BYTES + A_BYTES_CHUNK);
        for (int i = tid; i < ICK * BPIX; i += NTHR) B[i] = 0;
    }
    __syncthreads();

    float acc[2][8][4];
#pragma unroll
    for (int mi = 0; mi < 2; mi++)
#pragma unroll
        for (int ni = 0; ni < 8; ni++)
#pragma unroll
            for (int r = 0; r < 4; r++) acc[mi][ni][r] = 0.f;

    const float* xin = x + (size_t)n * CC * HHH * WID;

    // prologue: stage chunk 0
    stage_chunk(sb, 0, half, rg, tid, xin);

    for (int chunk = 0; chunk < NCHUNK; chunk++) {
        const uint32_t cur = sb + (chunk & 1) * STAGE_BYTES;
        asm volatile("cp.async.wait_group 0;" ::: "memory");
        __syncthreads();

        // prefetch next chunk into the other stage (overlaps compute below)
        if (chunk + 1 < NCHUNK)
            stage_chunk(sb + ((chunk + 1) & 1) * STAGE_BYTES, chunk + 1, half, rg, tid, xin);

        const float4*   Af = (const float4*)(smem + (chunk & 1) * STAGE_BYTES);
        const uint32_t* Bs = (const uint32_t*)(smem + (chunk & 1) * STAGE_BYTES + A_BYTES_CHUNK);

#pragma unroll
        for (int tap = 0; tap < 9; tap++) {
            const int kh = tap / 3, kw = tap - 3 * kh;
            const int prow = (warp_n + kh) * BCOLS + g + kw;
#pragma unroll
            for (int kstep = 0; kstep < 2; kstep++) {
                const int fbase = ((tap * 2 + kstep) * 8 + warp_m * 2) * 32 + lane;
                const float4 A0 = Af[fbase];
                const float4 A1 = Af[fbase + 32];
                const int kk = t4 + kstep * 8;
                const uint32_t* B0 = Bs + kk * BPIX + prow;
                const uint32_t* B1 = B0 + 4 * BPIX;
#pragma unroll
                for (int ni = 0; ni < 8; ni++) {
                    uint32_t b0 = B0[ni * 8];
                    uint32_t b1 = B1[ni * 8];
                    mma8(acc[0][ni], A0, b0, b1);
                    mma8(acc[1][ni], A1, b0, b1);
                }
            }
        }
        // barrier before buffer reuse: threads must finish reading `cur`
        // before the NEXT iteration's prefetch targets it (issued after wait+sync)
        if (chunk + 2 < NCHUNK) { /* reuse handled by top-of-loop sync */ }
    }

    // ---- epilogue
    const int oh = rg * 4 + warp_n;
    if (oh < OHH) {
#pragma unroll
        for (int mi = 0; mi < 2; mi++) {
            const int oc0 = half * 128 + warp_m * 32 + mi * 16 + g;
            const float bv0 = bias[oc0];
            const float bv1 = bias[oc0 + 8];
            float* o0 = out + ((size_t)n * OCH + oc0) * (OHH * OWW) + oh * OWW;
            float* o1 = o0 + 8 * (OHH * OWW);
#pragma unroll
            for (int ni = 0; ni < 7; ni++) {
                const int ow = ni * 8 + 2 * t4;
                if (ow < OWW) {
                    float2 v0 = make_float2(acc[mi][ni][0] + bv0, acc[mi][ni][1] + bv0);
                    float2 v1 = make_float2(acc[mi][ni][2] + bv1, acc[mi][ni][3] + bv1);
                    *(float2*)(o0 + ow) = v0;
                    *(float2*)(o1 + ow) = v1;
                }
            }
        }
    }
}

// ------------------------- launch -------------------------------------------
extern "C" void kernel_launch(void* const* d_in, const int* in_sizes, int n_in,
                              void* d_out, int out_size) {
    const float* x    = (const float*)d_in[0];
    const float* w    = (const float*)d_in[1];
    const float* bias = (const float*)d_in[2];
    float*       out  = (float*)d_out;

    k_init<<<1, 1>>>();
    k_max<<<256, 256>>>(w, OCH * CC * 9);
    k_quant<<<(2 * NCHUNK * A_FLOATS_CHUNK + 255) / 256, 256>>>(w);

    cudaFuncSetAttribute(k_conv, cudaFuncAttributeMaxDynamicSharedMemorySize, SMEM_DYN);
    dim3 grid(2, 14, 32);
    k_conv<<<grid, NTHR, SMEM_DYN>>>(x, bias, out);

    (void)in_sizes; (void)n_in; (void)out_size;
}